// round 14
// baseline (speedup 1.0000x reference)
#include <cuda_runtime.h>
#include <cuda_bf16.h>
#include <cstdint>

#define N_NODES 50000
#define EMBED_DIM 128
#define N_EDGES 500000
#define CAP 64
#define NBLK ((N_NODES + 255) / 256)   // 196

// ---------------- device scratch (zero-initialized at module load) ----------------
__device__ int   g_cursor[N_NODES];            // zero at entry; self-cleaned each run
__device__ int   g_deg[N_NODES];
__device__ float g_dis[N_NODES];
__device__ int   g_srcs[N_NODES * CAP];        // per-node src buckets
__device__ float g_agg[N_NODES * EMBED_DIM];
__device__ float g_h[N_NODES * EMBED_DIM];
// W split images, transposed: Bh[layer][n*128+k] = bf16_hi(W[k][n])
__device__ __nv_bfloat16 g_Bh[2][128 * 128];
__device__ __nv_bfloat16 g_Bl[2][128 * 128];

// ---------------- fill buckets (1 edge/thread) + fused weight prep ----------------
__global__ void k_fill(const int* __restrict__ ei,
                       const float* __restrict__ W1, const float* __restrict__ W2) {
    int e = blockIdx.x * blockDim.x + threadIdx.x;
    if (e < N_EDGES) {
        unsigned s = (unsigned)ei[e];
        unsigned d = (unsigned)ei[N_EDGES + e];
        if (s < N_NODES && d < N_NODES) {
            int pos = atomicAdd(&g_cursor[d], 1);
            if (pos < CAP) g_srcs[d * CAP + pos] = (int)s;
        }
    }
    // side job: weight split/transpose (first 128 blocks, 32768 elems)
    if (blockIdx.x < 128) {
        int idx = blockIdx.x * blockDim.x + threadIdx.x;
        int layer = idx >> 14;
        int t = idx & 16383;
        int k = t >> 7, n = t & 127;
        const float* W = layer ? W2 : W1;
        float w = W[k * 128 + n];
        __nv_bfloat16 wh = __float2bfloat16(w);
        __nv_bfloat16 wl = __float2bfloat16(w - __bfloat162float(wh));
        g_Bh[layer][n * 128 + k] = wh;
        g_Bl[layer][n * 128 + k] = wl;
    }
}

// ---------------- degree -> dis; self-clean cursor ----------------
__global__ __launch_bounds__(256) void k_dis() {
    int i = blockIdx.x * blockDim.x + threadIdx.x;
    if (i < N_NODES) {
        int c = g_cursor[i];
        if (c > CAP) c = CAP;
        g_deg[i] = c;
        g_dis[i] = rsqrtf((float)(c + 1));
        g_cursor[i] = 0;                  // ready for next graph replay
    }
}

// ---------------- gather-aggregate (warp per node, unroll 4) ----------------
// norm computed on the fly: nm_j = dis[node] * dis[src_j]
__global__ __launch_bounds__(256) void k_gather(const float* __restrict__ x, int use_h,
                                                float* __restrict__ out2) {
    int idx = blockIdx.x * blockDim.x + threadIdx.x;
    int node = idx >> 5;
    if (node >= N_NODES) return;
    const float* in = use_h ? g_h : x;
    int lane = idx & 31;

    float di = g_dis[node];
    float c = di * di;
    float4 raw = ((const float4*)(in + (size_t)node * EMBED_DIM))[lane];
    if (out2) ((float4*)(out2 + (size_t)node * EMBED_DIM))[lane] = raw;
    float4 acc;
    acc.x = raw.x * c; acc.y = raw.y * c; acc.z = raw.z * c; acc.w = raw.w * c;

    int deg = g_deg[node];
    const int* bucket = g_srcs + node * CAP;

    int j = 0;
    for (; j + 4 <= deg; j += 4) {
        int4 ss = *(const int4*)(bucket + j);     // broadcast LDG.128 for 4 srcs
        float n0 = di * g_dis[ss.x];
        float n1 = di * g_dis[ss.y];
        float n2 = di * g_dis[ss.z];
        float n3 = di * g_dis[ss.w];
        float4 v0 = ((const float4*)(in + (size_t)ss.x * EMBED_DIM))[lane];
        float4 v1 = ((const float4*)(in + (size_t)ss.y * EMBED_DIM))[lane];
        float4 v2 = ((const float4*)(in + (size_t)ss.z * EMBED_DIM))[lane];
        float4 v3 = ((const float4*)(in + (size_t)ss.w * EMBED_DIM))[lane];
        acc.x += n0 * v0.x + n1 * v1.x + n2 * v2.x + n3 * v3.x;
        acc.y += n0 * v0.y + n1 * v1.y + n2 * v2.y + n3 * v3.y;
        acc.z += n0 * v0.z + n1 * v1.z + n2 * v2.z + n3 * v3.z;
        acc.w += n0 * v0.w + n1 * v1.w + n2 * v2.w + n3 * v3.w;
    }
    for (; j < deg; j++) {
        int s0 = bucket[j];
        float n0 = di * g_dis[s0];
        float4 v0 = ((const float4*)(in + (size_t)s0 * EMBED_DIM))[lane];
        acc.x += n0 * v0.x; acc.y += n0 * v0.y;
        acc.z += n0 * v0.z; acc.w += n0 * v0.w;
    }
    ((float4*)(g_agg + (size_t)node * EMBED_DIM))[lane] = acc;
}

// ---------------- HMMA bf16x3 GEMM + bias + tanh — proven ----------------
#define PAD 136
#define A_IMG (64 * PAD * 2)
#define B_IMG (128 * PAD * 2)
#define SM_AH 0
#define SM_AL A_IMG
#define SM_BH (2 * A_IMG)
#define SM_BL (2 * A_IMG + B_IMG)
#define MMA_SMEM (2 * A_IMG + 2 * B_IMG)   // 104448 B

__device__ __forceinline__ uint32_t smem_u32(const void* p) {
    uint32_t a;
    asm("{ .reg .u64 t; cvta.to.shared.u64 t, %1; cvt.u32.u64 %0, t; }" : "=r"(a) : "l"(p));
    return a;
}
__device__ __forceinline__ void ldm_x4(uint32_t* r, uint32_t addr) {
    asm volatile("ldmatrix.sync.aligned.m8n8.x4.shared.b16 {%0,%1,%2,%3}, [%4];"
                 : "=r"(r[0]), "=r"(r[1]), "=r"(r[2]), "=r"(r[3]) : "r"(addr));
}
__device__ __forceinline__ void mma_bf16(float* d, const uint32_t* a, uint32_t b0, uint32_t b1) {
    asm volatile(
        "mma.sync.aligned.m16n8k16.row.col.f32.bf16.bf16.f32 "
        "{%0,%1,%2,%3}, {%4,%5,%6,%7}, {%8,%9}, {%0,%1,%2,%3};"
        : "+f"(d[0]), "+f"(d[1]), "+f"(d[2]), "+f"(d[3])
        : "r"(a[0]), "r"(a[1]), "r"(a[2]), "r"(a[3]), "r"(b0), "r"(b1));
}

__global__ __launch_bounds__(256) void k_mma_gemm(const float* __restrict__ bvec,
                                                  float* __restrict__ out,
                                                  int layer, int to_h) {
    extern __shared__ char sm[];
    __nv_bfloat16* sAH = (__nv_bfloat16*)(sm + SM_AH);
    __nv_bfloat16* sAL = (__nv_bfloat16*)(sm + SM_AL);
    int tid = threadIdx.x, wid = tid >> 5, lane = tid & 31;
    int row0 = blockIdx.x * 64;
    float* dst = to_h ? g_h : out;

    {
        const uint4* bh = (const uint4*)g_Bh[layer];
        const uint4* bl = (const uint4*)g_Bl[layer];
        #pragma unroll
        for (int i = 0; i < 8; i++) {
            int idx = tid + i * 256;
            int n = idx >> 4, c = idx & 15;
            *(uint4*)(sm + SM_BH + n * (PAD * 2) + c * 16) = bh[idx];
            *(uint4*)(sm + SM_BL + n * (PAD * 2) + c * 16) = bl[idx];
        }
    }
    #pragma unroll
    for (int i = 0; i < 32; i++) {
        int idx = tid + i * 256;
        int r = idx >> 7, k = idx & 127;
        int gr = row0 + r;
        float a = (gr < N_NODES) ? g_agg[(size_t)gr * EMBED_DIM + k] : 0.0f;
        __nv_bfloat16 ah = __float2bfloat16(a);
        __nv_bfloat16 al = __float2bfloat16(a - __bfloat162float(ah));
        sAH[r * PAD + k] = ah;
        sAL[r * PAD + k] = al;
    }
    __syncthreads();

    int m0 = (wid & 3) * 16;
    int n_base = (wid >> 2) * 64;

    uint32_t sb = smem_u32(sm);
    uint32_t aoff = (uint32_t)((m0 + (lane & 15)) * (PAD * 2) + (lane & 16));
    uint32_t aAddrH = sb + SM_AH + aoff;
    uint32_t aAddrL = sb + SM_AL + aoff;
    uint32_t bAddrH[4], bAddrL[4];
    #pragma unroll
    for (int p = 0; p < 4; p++) {
        int n = n_base + p * 16 + (lane & 7) + ((lane >> 1) & 8);
        uint32_t boff = (uint32_t)(n * (PAD * 2) + (lane & 8) * 2);
        bAddrH[p] = sb + SM_BH + boff;
        bAddrL[p] = sb + SM_BL + boff;
    }

    float d[8][4];
    #pragma unroll
    for (int t = 0; t < 8; t++)
        #pragma unroll
        for (int q = 0; q < 4; q++) d[t][q] = 0.0f;

    #pragma unroll
    for (int kk = 0; kk < 8; kk++) {
        uint32_t kb = kk * 32;
        uint32_t ah[4], al[4], bh[4][4], bl[4][4];
        ldm_x4(ah, aAddrH + kb);
        ldm_x4(al, aAddrL + kb);
        #pragma unroll
        for (int p = 0; p < 4; p++) {
            ldm_x4(bh[p], bAddrH[p] + kb);
            ldm_x4(bl[p], bAddrL[p] + kb);
        }
        #pragma unroll
        for (int p = 0; p < 4; p++) {
            #pragma unroll
            for (int q = 0; q < 2; q++) {
                int t = p * 2 + q;
                mma_bf16(d[t], ah, bh[p][2 * q], bh[p][2 * q + 1]);
                mma_bf16(d[t], ah, bl[p][2 * q], bl[p][2 * q + 1]);
                mma_bf16(d[t], al, bh[p][2 * q], bh[p][2 * q + 1]);
            }
        }
    }

    int g = lane >> 2;
    int c2 = (lane & 3) * 2;
    int rowA = row0 + m0 + g;
    int rowB = rowA + 8;
    #pragma unroll
    for (int t = 0; t < 8; t++) {
        int col = n_base + t * 8 + c2;
        float bx = bvec[col], by = bvec[col + 1];
        if (rowA < N_NODES) {
            float2 o;
            o.x = tanhf(d[t][0] + bx);
            o.y = tanhf(d[t][1] + by);
            *(float2*)(dst + (size_t)rowA * EMBED_DIM + col) = o;
        }
        if (rowB < N_NODES) {
            float2 o;
            o.x = tanhf(d[t][2] + bx);
            o.y = tanhf(d[t][3] + by);
            *(float2*)(dst + (size_t)rowB * EMBED_DIM + col) = o;
        }
    }
}

extern "C" void kernel_launch(void* const* d_in, const int* in_sizes, int n_in,
                              void* d_out, int out_size) {
    const float* x  = (const float*)d_in[0];
    const int*   ei = (const int*)d_in[1];
    const float* W1 = (const float*)d_in[2];
    const float* b1 = (const float*)d_in[3];
    const float* W2 = (const float*)d_in[4];
    const float* b2 = (const float*)d_in[5];
    float* out = (float*)d_out;

    cudaFuncSetAttribute(k_mma_gemm,
                         cudaFuncAttributeMaxDynamicSharedMemorySize, MMA_SMEM);

    const int NT = 256;
    int blksE  = (N_EDGES + NT - 1) / NT;        // 1954
    int blksND = (N_NODES * 32 + NT - 1) / NT;   // 6250
    int blksG  = (N_NODES + 63) / 64;            // 782

    // bucketized adjacency build (no histogram, no scan)
    k_fill<<<blksE, NT>>>(ei, W1, W2);
    k_dis<<<NBLK, NT>>>();

    float* out2 = (out_size >= 2 * N_NODES * EMBED_DIM)
                ? out + (size_t)N_NODES * EMBED_DIM : nullptr;

    // layer 1 (gather also writes the identity copy of x)
    k_gather<<<blksND, NT>>>(x, 0, out2);
    k_mma_gemm<<<blksG, NT, MMA_SMEM>>>(b1, out, 0, 1);

    // layer 2
    k_gather<<<blksND, NT>>>(x, 1, nullptr);
    k_mma_gemm<<<blksG, NT, MMA_SMEM>>>(b2, out, 1, 0);
}

// round 15
// speedup vs baseline: 1.0368x; 1.0368x over previous
#include <cuda_runtime.h>
#include <cuda_bf16.h>
#include <cstdint>

#define N_NODES 50000
#define EMBED_DIM 128
#define N_EDGES 500000
#define NBLK ((N_NODES + 255) / 256)   // 196

// ---------------- device scratch (zero-initialized at module load) ----------------
__device__ int   g_cnt[N_NODES];          // self-cleaning histogram
__device__ int   g_bsum[NBLK];
__device__ int   g_rowstart[N_NODES + 1];
__device__ int   g_cursor[N_NODES];
__device__ unsigned long long g_edge[N_EDGES];   // packed {val_f32<<32 | col}
__device__ float g_dis[N_NODES];
__device__ float g_agg[N_NODES * EMBED_DIM];
__device__ float g_h[N_NODES * EMBED_DIM];
// W split images, transposed: Bh[layer][n*128+k] = bf16_hi(W[k][n])
__device__ __nv_bfloat16 g_Bh[2][128 * 128];
__device__ __nv_bfloat16 g_Bl[2][128 * 128];

__device__ __forceinline__ float fast_tanh(float x) {
    float y;
    asm("tanh.approx.f32 %0, %1;" : "=f"(y) : "f"(x));
    return y;
}

// ---------------- hist (1 edge/thread, fused weight prep) ----------------
__global__ void k_hist(const int* __restrict__ ei,
                       const float* __restrict__ W1, const float* __restrict__ W2) {
    int e = blockIdx.x * blockDim.x + threadIdx.x;
    if (e < N_EDGES) {
        unsigned d = (unsigned)ei[N_EDGES + e];
        if (d < N_NODES) atomicAdd(&g_cnt[d], 1);
    }
    if (blockIdx.x < 128) {
        int idx = blockIdx.x * blockDim.x + threadIdx.x;
        int layer = idx >> 14;
        int t = idx & 16383;
        int k = t >> 7, n = t & 127;
        const float* W = layer ? W2 : W1;
        float w = W[k * 128 + n];
        __nv_bfloat16 wh = __float2bfloat16(w);
        __nv_bfloat16 wl = __float2bfloat16(w - __bfloat162float(wh));
        g_Bh[layer][n * 128 + k] = wh;
        g_Bl[layer][n * 128 + k] = wl;
    }
}

// ---------------- warp-shuffle block sum ----------------
__global__ __launch_bounds__(256) void k_blocksum() {
    int t = threadIdx.x;
    int i = blockIdx.x * 256 + t;
    int v = (i < N_NODES) ? g_cnt[i] : 0;
    #pragma unroll
    for (int off = 16; off > 0; off >>= 1) v += __shfl_down_sync(0xffffffffu, v, off);
    __shared__ int ws[8];
    if ((t & 31) == 0) ws[t >> 5] = v;
    __syncthreads();
    if (t == 0) {
        int s = 0;
        #pragma unroll
        for (int w = 0; w < 8; w++) s += ws[w];
        g_bsum[blockIdx.x] = s;
    }
}

// ---------------- warp-shuffle scan (2 barriers) ----------------
__global__ __launch_bounds__(256) void k_scan_final() {
    int t = threadIdx.x;
    int lane = t & 31, warp = t >> 5;
    int i = blockIdx.x * 256 + t;

    int b = (t < blockIdx.x) ? g_bsum[t] : 0;   // NBLK=196 < 256
    #pragma unroll
    for (int off = 16; off > 0; off >>= 1) b += __shfl_down_sync(0xffffffffu, b, off);
    __shared__ int ws[8], wt[8], s_blockoff;
    if (lane == 0) ws[warp] = b;

    int v = (i < N_NODES) ? g_cnt[i] : 0;
    int incl = v;
    #pragma unroll
    for (int off = 1; off < 32; off <<= 1) {
        int n = __shfl_up_sync(0xffffffffu, incl, off);
        if (lane >= off) incl += n;
    }
    if (lane == 31) wt[warp] = incl;
    __syncthreads();
    if (t == 0) {
        int s = 0;
        #pragma unroll
        for (int w = 0; w < 8; w++) s += ws[w];
        s_blockoff = s;
    }
    __syncthreads();
    int warpbase = 0;
    #pragma unroll
    for (int w = 0; w < 8; w++) if (w < warp) warpbase += wt[w];

    if (i < N_NODES) {
        int rs = s_blockoff + warpbase + incl - v;
        g_rowstart[i] = rs;
        g_cursor[i]   = rs;
        g_dis[i]      = rsqrtf((float)(v + 1));
        g_cnt[i]      = 0;
    }
    if (i == 0) g_rowstart[N_NODES] = N_EDGES;
}

// ---------------- fill (1 edge/thread) ----------------
__global__ void k_fill(const int* __restrict__ ei) {
    int e = blockIdx.x * blockDim.x + threadIdx.x;
    if (e >= N_EDGES) return;
    unsigned s = (unsigned)ei[e];
    unsigned d = (unsigned)ei[N_EDGES + e];
    if (s >= N_NODES || d >= N_NODES) return;
    int pos = atomicAdd(&g_cursor[d], 1);
    float nm = g_dis[s] * g_dis[d];
    g_edge[pos] = ((unsigned long long)__float_as_uint(nm) << 32) | (unsigned long long)s;
}

// ---------------- gather-aggregate (warp per node, unroll 4) ----------------
__global__ __launch_bounds__(256) void k_gather(const float* __restrict__ x, int use_h,
                                                float* __restrict__ out2) {
    int idx = blockIdx.x * blockDim.x + threadIdx.x;
    int node = idx >> 5;
    if (node >= N_NODES) return;
    const float* in = use_h ? g_h : x;
    int lane = idx & 31;

    float di = g_dis[node];
    float c = di * di;
    float4 raw = ((const float4*)(in + (size_t)node * EMBED_DIM))[lane];
    if (out2) ((float4*)(out2 + (size_t)node * EMBED_DIM))[lane] = raw;
    float4 acc;
    acc.x = raw.x * c; acc.y = raw.y * c; acc.z = raw.z * c; acc.w = raw.w * c;

    int j   = g_rowstart[node];
    int end = g_rowstart[node + 1];

    for (; j + 4 <= end; j += 4) {
        unsigned long long p0 = g_edge[j],     p1 = g_edge[j + 1];
        unsigned long long p2 = g_edge[j + 2], p3 = g_edge[j + 3];
        int s0 = (int)(unsigned)p0, s1 = (int)(unsigned)p1;
        int s2 = (int)(unsigned)p2, s3 = (int)(unsigned)p3;
        float n0 = __uint_as_float((unsigned)(p0 >> 32));
        float n1 = __uint_as_float((unsigned)(p1 >> 32));
        float n2 = __uint_as_float((unsigned)(p2 >> 32));
        float n3 = __uint_as_float((unsigned)(p3 >> 32));
        float4 v0 = ((const float4*)(in + (size_t)s0 * EMBED_DIM))[lane];
        float4 v1 = ((const float4*)(in + (size_t)s1 * EMBED_DIM))[lane];
        float4 v2 = ((const float4*)(in + (size_t)s2 * EMBED_DIM))[lane];
        float4 v3 = ((const float4*)(in + (size_t)s3 * EMBED_DIM))[lane];
        acc.x += n0 * v0.x + n1 * v1.x + n2 * v2.x + n3 * v3.x;
        acc.y += n0 * v0.y + n1 * v1.y + n2 * v2.y + n3 * v3.y;
        acc.z += n0 * v0.z + n1 * v1.z + n2 * v2.z + n3 * v3.z;
        acc.w += n0 * v0.w + n1 * v1.w + n2 * v2.w + n3 * v3.w;
    }
    for (; j < end; j++) {
        unsigned long long p0 = g_edge[j];
        int s0 = (int)(unsigned)p0;
        float n0 = __uint_as_float((unsigned)(p0 >> 32));
        float4 v0 = ((const float4*)(in + (size_t)s0 * EMBED_DIM))[lane];
        acc.x += n0 * v0.x; acc.y += n0 * v0.y;
        acc.z += n0 * v0.z; acc.w += n0 * v0.w;
    }
    ((float4*)(g_agg + (size_t)node * EMBED_DIM))[lane] = acc;
}

// ---------------- HMMA bf16x3 GEMM + bias + fast tanh ----------------
#define PAD 136
#define A_IMG (64 * PAD * 2)
#define B_IMG (128 * PAD * 2)
#define SM_AH 0
#define SM_AL A_IMG
#define SM_BH (2 * A_IMG)
#define SM_BL (2 * A_IMG + B_IMG)
#define MMA_SMEM (2 * A_IMG + 2 * B_IMG)   // 104448 B

__device__ __forceinline__ uint32_t smem_u32(const void* p) {
    uint32_t a;
    asm("{ .reg .u64 t; cvta.to.shared.u64 t, %1; cvt.u32.u64 %0, t; }" : "=r"(a) : "l"(p));
    return a;
}
__device__ __forceinline__ void ldm_x4(uint32_t* r, uint32_t addr) {
    asm volatile("ldmatrix.sync.aligned.m8n8.x4.shared.b16 {%0,%1,%2,%3}, [%4];"
                 : "=r"(r[0]), "=r"(r[1]), "=r"(r[2]), "=r"(r[3]) : "r"(addr));
}
__device__ __forceinline__ void mma_bf16(float* d, const uint32_t* a, uint32_t b0, uint32_t b1) {
    asm volatile(
        "mma.sync.aligned.m16n8k16.row.col.f32.bf16.bf16.f32 "
        "{%0,%1,%2,%3}, {%4,%5,%6,%7}, {%8,%9}, {%0,%1,%2,%3};"
        : "+f"(d[0]), "+f"(d[1]), "+f"(d[2]), "+f"(d[3])
        : "r"(a[0]), "r"(a[1]), "r"(a[2]), "r"(a[3]), "r"(b0), "r"(b1));
}

__global__ __launch_bounds__(256) void k_mma_gemm(const float* __restrict__ bvec,
                                                  float* __restrict__ out,
                                                  int layer, int to_h) {
    extern __shared__ char sm[];
    __nv_bfloat16* sAH = (__nv_bfloat16*)(sm + SM_AH);
    __nv_bfloat16* sAL = (__nv_bfloat16*)(sm + SM_AL);
    int tid = threadIdx.x, wid = tid >> 5, lane = tid & 31;
    int row0 = blockIdx.x * 64;
    float* dst = to_h ? g_h : out;

    {
        const uint4* bh = (const uint4*)g_Bh[layer];
        const uint4* bl = (const uint4*)g_Bl[layer];
        #pragma unroll
        for (int i = 0; i < 8; i++) {
            int idx = tid + i * 256;
            int n = idx >> 4, c = idx & 15;
            *(uint4*)(sm + SM_BH + n * (PAD * 2) + c * 16) = bh[idx];
            *(uint4*)(sm + SM_BL + n * (PAD * 2) + c * 16) = bl[idx];
        }
    }
    #pragma unroll
    for (int i = 0; i < 32; i++) {
        int idx = tid + i * 256;
        int r = idx >> 7, k = idx & 127;
        int gr = row0 + r;
        float a = (gr < N_NODES) ? g_agg[(size_t)gr * EMBED_DIM + k] : 0.0f;
        __nv_bfloat16 ah = __float2bfloat16(a);
        __nv_bfloat16 al = __float2bfloat16(a - __bfloat162float(ah));
        sAH[r * PAD + k] = ah;
        sAL[r * PAD + k] = al;
    }
    __syncthreads();

    int m0 = (wid & 3) * 16;
    int n_base = (wid >> 2) * 64;

    uint32_t sb = smem_u32(sm);
    uint32_t aoff = (uint32_t)((m0 + (lane & 15)) * (PAD * 2) + (lane & 16));
    uint32_t aAddrH = sb + SM_AH + aoff;
    uint32_t aAddrL = sb + SM_AL + aoff;
    uint32_t bAddrH[4], bAddrL[4];
    #pragma unroll
    for (int p = 0; p < 4; p++) {
        int n = n_base + p * 16 + (lane & 7) + ((lane >> 1) & 8);
        uint32_t boff = (uint32_t)(n * (PAD * 2) + (lane & 8) * 2);
        bAddrH[p] = sb + SM_BH + boff;
        bAddrL[p] = sb + SM_BL + boff;
    }

    float d[8][4];
    #pragma unroll
    for (int t = 0; t < 8; t++)
        #pragma unroll
        for (int q = 0; q < 4; q++) d[t][q] = 0.0f;

    #pragma unroll
    for (int kk = 0; kk < 8; kk++) {
        uint32_t kb = kk * 32;
        uint32_t ah[4], al[4], bh[4][4], bl[4][4];
        ldm_x4(ah, aAddrH + kb);
        ldm_x4(al, aAddrL + kb);
        #pragma unroll
        for (int p = 0; p < 4; p++) {
            ldm_x4(bh[p], bAddrH[p] + kb);
            ldm_x4(bl[p], bAddrL[p] + kb);
        }
        #pragma unroll
        for (int p = 0; p < 4; p++) {
            #pragma unroll
            for (int q = 0; q < 2; q++) {
                int t = p * 2 + q;
                mma_bf16(d[t], ah, bh[p][2 * q], bh[p][2 * q + 1]);
                mma_bf16(d[t], ah, bl[p][2 * q], bl[p][2 * q + 1]);
                mma_bf16(d[t], al, bh[p][2 * q], bh[p][2 * q + 1]);
            }
        }
    }

    int g = lane >> 2;
    int c2 = (lane & 3) * 2;
    int rowA = row0 + m0 + g;
    int rowB = rowA + 8;
    #pragma unroll
    for (int t = 0; t < 8; t++) {
        int col = n_base + t * 8 + c2;
        float bx = bvec[col], by = bvec[col + 1];
        if (rowA < N_NODES) {
            float2 o;
            o.x = fast_tanh(d[t][0] + bx);
            o.y = fast_tanh(d[t][1] + by);
            *(float2*)(dst + (size_t)rowA * EMBED_DIM + col) = o;
        }
        if (rowB < N_NODES) {
            float2 o;
            o.x = fast_tanh(d[t][2] + bx);
            o.y = fast_tanh(d[t][3] + by);
            *(float2*)(dst + (size_t)rowB * EMBED_DIM + col) = o;
        }
    }
}

extern "C" void kernel_launch(void* const* d_in, const int* in_sizes, int n_in,
                              void* d_out, int out_size) {
    const float* x  = (const float*)d_in[0];
    const int*   ei = (const int*)d_in[1];
    const float* W1 = (const float*)d_in[2];
    const float* b1 = (const float*)d_in[3];
    const float* W2 = (const float*)d_in[4];
    const float* b2 = (const float*)d_in[5];
    float* out = (float*)d_out;

    cudaFuncSetAttribute(k_mma_gemm,
                         cudaFuncAttributeMaxDynamicSharedMemorySize, MMA_SMEM);

    const int NT = 256;
    int blksE  = (N_EDGES + NT - 1) / NT;        // 1954
    int blksND = (N_NODES * 32 + NT - 1) / NT;   // 6250
    int blksG  = (N_NODES + 63) / 64;            // 782

    // CSR build (g_cnt zero at entry; self-cleaned in scan)
    k_hist<<<blksE, NT>>>(ei, W1, W2);
    k_blocksum<<<NBLK, NT>>>();
    k_scan_final<<<NBLK, NT>>>();
    k_fill<<<blksE, NT>>>(ei);

    float* out2 = (out_size >= 2 * N_NODES * EMBED_DIM)
                ? out + (size_t)N_NODES * EMBED_DIM : nullptr;

    // layer 1 (gather also writes the identity copy of x)
    k_gather<<<blksND, NT>>>(x, 0, out2);
    k_mma_gemm<<<blksG, NT, MMA_SMEM>>>(b1, out, 0, 1);

    // layer 2
    k_gather<<<blksND, NT>>>(x, 1, nullptr);
    k_mma_gemm<<<blksG, NT, MMA_SMEM>>>(b2, out, 1, 0);
}

// round 16
// speedup vs baseline: 1.0740x; 1.0359x over previous
#include <cuda_runtime.h>
#include <cuda_bf16.h>
#include <cstdint>

#define N_NODES 50000
#define EMBED_DIM 128
#define N_EDGES 500000
#define NBLK ((N_NODES + 255) / 256)   // 196
#define N_TILES ((N_NODES + 63) / 64)  // 782
#define N_ROWS_PAD (N_TILES * 64)      // 50048

// ---------------- device scratch (zero-initialized at module load) ----------------
__device__ int   g_cnt[N_NODES];          // self-cleaning histogram
__device__ int   g_bsum[NBLK];
__device__ int   g_rowstart[N_NODES + 1];
__device__ int   g_cursor[N_NODES];
__device__ unsigned long long g_edge[N_EDGES];   // packed {val_f32<<32 | col}
__device__ float g_dis[N_NODES];
__device__ __nv_bfloat16 g_aggh[N_ROWS_PAD * EMBED_DIM];  // agg hi image
__device__ __nv_bfloat16 g_aggl[N_ROWS_PAD * EMBED_DIM];  // agg lo image
__device__ float g_h[N_NODES * EMBED_DIM];
// W split images, transposed: Bh[layer][n*128+k] = bf16_hi(W[k][n])
__device__ __nv_bfloat16 g_Bh[2][128 * 128];
__device__ __nv_bfloat16 g_Bl[2][128 * 128];

__device__ __forceinline__ float fast_tanh(float x) {
    float y;
    asm("tanh.approx.f32 %0, %1;" : "=f"(y) : "f"(x));
    return y;
}

// ---------------- hist (1 edge/thread, fused weight prep) ----------------
__global__ void k_hist(const int* __restrict__ ei,
                       const float* __restrict__ W1, const float* __restrict__ W2) {
    int e = blockIdx.x * blockDim.x + threadIdx.x;
    if (e < N_EDGES) {
        unsigned d = (unsigned)ei[N_EDGES + e];
        if (d < N_NODES) atomicAdd(&g_cnt[d], 1);
    }
    if (blockIdx.x < 128) {
        int idx = blockIdx.x * blockDim.x + threadIdx.x;
        int layer = idx >> 14;
        int t = idx & 16383;
        int k = t >> 7, n = t & 127;
        const float* W = layer ? W2 : W1;
        float w = W[k * 128 + n];
        __nv_bfloat16 wh = __float2bfloat16(w);
        __nv_bfloat16 wl = __float2bfloat16(w - __bfloat162float(wh));
        g_Bh[layer][n * 128 + k] = wh;
        g_Bl[layer][n * 128 + k] = wl;
    }
}

// ---------------- warp-shuffle block sum ----------------
__global__ __launch_bounds__(256) void k_blocksum() {
    int t = threadIdx.x;
    int i = blockIdx.x * 256 + t;
    int v = (i < N_NODES) ? g_cnt[i] : 0;
    #pragma unroll
    for (int off = 16; off > 0; off >>= 1) v += __shfl_down_sync(0xffffffffu, v, off);
    __shared__ int ws[8];
    if ((t & 31) == 0) ws[t >> 5] = v;
    __syncthreads();
    if (t == 0) {
        int s = 0;
        #pragma unroll
        for (int w = 0; w < 8; w++) s += ws[w];
        g_bsum[blockIdx.x] = s;
    }
}

// ---------------- warp-shuffle scan (2 barriers) ----------------
__global__ __launch_bounds__(256) void k_scan_final() {
    int t = threadIdx.x;
    int lane = t & 31, warp = t >> 5;
    int i = blockIdx.x * 256 + t;

    int b = (t < blockIdx.x) ? g_bsum[t] : 0;
    #pragma unroll
    for (int off = 16; off > 0; off >>= 1) b += __shfl_down_sync(0xffffffffu, b, off);
    __shared__ int ws[8], wt[8], s_blockoff;
    if (lane == 0) ws[warp] = b;

    int v = (i < N_NODES) ? g_cnt[i] : 0;
    int incl = v;
    #pragma unroll
    for (int off = 1; off < 32; off <<= 1) {
        int n = __shfl_up_sync(0xffffffffu, incl, off);
        if (lane >= off) incl += n;
    }
    if (lane == 31) wt[warp] = incl;
    __syncthreads();
    if (t == 0) {
        int s = 0;
        #pragma unroll
        for (int w = 0; w < 8; w++) s += ws[w];
        s_blockoff = s;
    }
    __syncthreads();
    int warpbase = 0;
    #pragma unroll
    for (int w = 0; w < 8; w++) if (w < warp) warpbase += wt[w];

    if (i < N_NODES) {
        int rs = s_blockoff + warpbase + incl - v;
        g_rowstart[i] = rs;
        g_cursor[i]   = rs;
        g_dis[i]      = rsqrtf((float)(v + 1));
        g_cnt[i]      = 0;
    }
    if (i == 0) g_rowstart[N_NODES] = N_EDGES;
}

// ---------------- fill (1 edge/thread) ----------------
__global__ void k_fill(const int* __restrict__ ei) {
    int e = blockIdx.x * blockDim.x + threadIdx.x;
    if (e >= N_EDGES) return;
    unsigned s = (unsigned)ei[e];
    unsigned d = (unsigned)ei[N_EDGES + e];
    if (s >= N_NODES || d >= N_NODES) return;
    int pos = atomicAdd(&g_cursor[d], 1);
    float nm = g_dis[s] * g_dis[d];
    g_edge[pos] = ((unsigned long long)__float_as_uint(nm) << 32) | (unsigned long long)s;
}

// ---------------- gather-aggregate (warp per node); writes split bf16 images ----------------
__global__ __launch_bounds__(256) void k_gather(const float* __restrict__ x, int use_h,
                                                float* __restrict__ out2) {
    int idx = blockIdx.x * blockDim.x + threadIdx.x;
    int node = idx >> 5;
    if (node >= N_NODES) return;
    const float* in = use_h ? g_h : x;
    int lane = idx & 31;

    float di = g_dis[node];
    float c = di * di;
    float4 raw = ((const float4*)(in + (size_t)node * EMBED_DIM))[lane];
    if (out2) ((float4*)(out2 + (size_t)node * EMBED_DIM))[lane] = raw;
    float4 acc;
    acc.x = raw.x * c; acc.y = raw.y * c; acc.z = raw.z * c; acc.w = raw.w * c;

    int j   = g_rowstart[node];
    int end = g_rowstart[node + 1];

    for (; j + 4 <= end; j += 4) {
        unsigned long long p0 = g_edge[j],     p1 = g_edge[j + 1];
        unsigned long long p2 = g_edge[j + 2], p3 = g_edge[j + 3];
        int s0 = (int)(unsigned)p0, s1 = (int)(unsigned)p1;
        int s2 = (int)(unsigned)p2, s3 = (int)(unsigned)p3;
        float n0 = __uint_as_float((unsigned)(p0 >> 32));
        float n1 = __uint_as_float((unsigned)(p1 >> 32));
        float n2 = __uint_as_float((unsigned)(p2 >> 32));
        float n3 = __uint_as_float((unsigned)(p3 >> 32));
        float4 v0 = ((const float4*)(in + (size_t)s0 * EMBED_DIM))[lane];
        float4 v1 = ((const float4*)(in + (size_t)s1 * EMBED_DIM))[lane];
        float4 v2 = ((const float4*)(in + (size_t)s2 * EMBED_DIM))[lane];
        float4 v3 = ((const float4*)(in + (size_t)s3 * EMBED_DIM))[lane];
        acc.x += n0 * v0.x + n1 * v1.x + n2 * v2.x + n3 * v3.x;
        acc.y += n0 * v0.y + n1 * v1.y + n2 * v2.y + n3 * v3.y;
        acc.z += n0 * v0.z + n1 * v1.z + n2 * v2.z + n3 * v3.z;
        acc.w += n0 * v0.w + n1 * v1.w + n2 * v2.w + n3 * v3.w;
    }
    for (; j < end; j++) {
        unsigned long long p0 = g_edge[j];
        int s0 = (int)(unsigned)p0;
        float n0 = __uint_as_float((unsigned)(p0 >> 32));
        float4 v0 = ((const float4*)(in + (size_t)s0 * EMBED_DIM))[lane];
        acc.x += n0 * v0.x; acc.y += n0 * v0.y;
        acc.z += n0 * v0.z; acc.w += n0 * v0.w;
    }

    // split to bf16 hi/lo packed images (8B each)
    union { __nv_bfloat16 h[4]; uint2 u; } ph, pl;
    float av[4] = {acc.x, acc.y, acc.z, acc.w};
    #pragma unroll
    for (int q = 0; q < 4; q++) {
        __nv_bfloat16 hh = __float2bfloat16(av[q]);
        ph.h[q] = hh;
        pl.h[q] = __float2bfloat16(av[q] - __bfloat162float(hh));
    }
    ((uint2*)(g_aggh + (size_t)node * EMBED_DIM))[lane] = ph.u;
    ((uint2*)(g_aggl + (size_t)node * EMBED_DIM))[lane] = pl.u;
}

// ---------------- HMMA bf16x3 GEMM + bias + fast tanh ----------------
#define PAD 136
#define A_IMG (64 * PAD * 2)
#define B_IMG (128 * PAD * 2)
#define SM_AH 0
#define SM_AL A_IMG
#define SM_BH (2 * A_IMG)
#define SM_BL (2 * A_IMG + B_IMG)
#define MMA_SMEM (2 * A_IMG + 2 * B_IMG)   // 104448 B

__device__ __forceinline__ uint32_t smem_u32(const void* p) {
    uint32_t a;
    asm("{ .reg .u64 t; cvta.to.shared.u64 t, %1; cvt.u32.u64 %0, t; }" : "=r"(a) : "l"(p));
    return a;
}
__device__ __forceinline__ void ldm_x4(uint32_t* r, uint32_t addr) {
    asm volatile("ldmatrix.sync.aligned.m8n8.x4.shared.b16 {%0,%1,%2,%3}, [%4];"
                 : "=r"(r[0]), "=r"(r[1]), "=r"(r[2]), "=r"(r[3]) : "r"(addr));
}
__device__ __forceinline__ void mma_bf16(float* d, const uint32_t* a, uint32_t b0, uint32_t b1) {
    asm volatile(
        "mma.sync.aligned.m16n8k16.row.col.f32.bf16.bf16.f32 "
        "{%0,%1,%2,%3}, {%4,%5,%6,%7}, {%8,%9}, {%0,%1,%2,%3};"
        : "+f"(d[0]), "+f"(d[1]), "+f"(d[2]), "+f"(d[3])
        : "r"(a[0]), "r"(a[1]), "r"(a[2]), "r"(a[3]), "r"(b0), "r"(b1));
}

__global__ __launch_bounds__(256) void k_mma_gemm(const float* __restrict__ bvec,
                                                  float* __restrict__ out,
                                                  int layer, int to_h) {
    extern __shared__ char sm[];
    int tid = threadIdx.x, wid = tid >> 5, lane = tid & 31;
    int row0 = blockIdx.x * 64;
    float* dst = to_h ? g_h : out;

    // stage B images (pure copies)
    {
        const uint4* bh = (const uint4*)g_Bh[layer];
        const uint4* bl = (const uint4*)g_Bl[layer];
        #pragma unroll
        for (int i = 0; i < 8; i++) {
            int idx = tid + i * 256;
            int n = idx >> 4, c = idx & 15;
            *(uint4*)(sm + SM_BH + n * (PAD * 2) + c * 16) = bh[idx];
            *(uint4*)(sm + SM_BL + n * (PAD * 2) + c * 16) = bl[idx];
        }
    }
    // stage A images (pure copies; rows pre-split by gather, padding rows zero)
    {
        const uint4* ah = (const uint4*)(g_aggh + (size_t)row0 * EMBED_DIM);
        const uint4* al = (const uint4*)(g_aggl + (size_t)row0 * EMBED_DIM);
        #pragma unroll
        for (int i = 0; i < 4; i++) {
            int idx = tid + i * 256;            // 1024 uint4 = 64 rows x 16
            int r = idx >> 4, c = idx & 15;
            *(uint4*)(sm + SM_AH + r * (PAD * 2) + c * 16) = ah[idx];
            *(uint4*)(sm + SM_AL + r * (PAD * 2) + c * 16) = al[idx];
        }
    }
    __syncthreads();

    int m0 = (wid & 3) * 16;
    int n_base = (wid >> 2) * 64;

    uint32_t sb = smem_u32(sm);
    uint32_t aoff = (uint32_t)((m0 + (lane & 15)) * (PAD * 2) + (lane & 16));
    uint32_t aAddrH = sb + SM_AH + aoff;
    uint32_t aAddrL = sb + SM_AL + aoff;
    uint32_t bAddrH[4], bAddrL[4];
    #pragma unroll
    for (int p = 0; p < 4; p++) {
        int n = n_base + p * 16 + (lane & 7) + ((lane >> 1) & 8);
        uint32_t boff = (uint32_t)(n * (PAD * 2) + (lane & 8) * 2);
        bAddrH[p] = sb + SM_BH + boff;
        bAddrL[p] = sb + SM_BL + boff;
    }

    float d[8][4], d2[8][4];
    #pragma unroll
    for (int t = 0; t < 8; t++)
        #pragma unroll
        for (int q = 0; q < 4; q++) { d[t][q] = 0.0f; d2[t][q] = 0.0f; }

    #pragma unroll
    for (int kk = 0; kk < 8; kk++) {
        uint32_t kb = kk * 32;
        uint32_t ah[4], al[4], bh[4][4], bl[4][4];
        ldm_x4(ah, aAddrH + kb);
        ldm_x4(al, aAddrL + kb);
        #pragma unroll
        for (int p = 0; p < 4; p++) {
            ldm_x4(bh[p], bAddrH[p] + kb);
            ldm_x4(bl[p], bAddrL[p] + kb);
        }
        #pragma unroll
        for (int p = 0; p < 4; p++) {
            #pragma unroll
            for (int q = 0; q < 2; q++) {
                int t = p * 2 + q;
                mma_bf16(d[t],  ah, bh[p][2 * q], bh[p][2 * q + 1]);   // Ah*Bh
                mma_bf16(d2[t], ah, bl[p][2 * q], bl[p][2 * q + 1]);   // Ah*Bl
                mma_bf16(d2[t], al, bh[p][2 * q], bh[p][2 * q + 1]);   // Al*Bh
            }
        }
    }

    int g = lane >> 2;
    int c2 = (lane & 3) * 2;
    int rowA = row0 + m0 + g;
    int rowB = rowA + 8;
    #pragma unroll
    for (int t = 0; t < 8; t++) {
        int col = n_base + t * 8 + c2;
        float bx = bvec[col], by = bvec[col + 1];
        if (rowA < N_NODES) {
            float2 o;
            o.x = fast_tanh(d[t][0] + d2[t][0] + bx);
            o.y = fast_tanh(d[t][1] + d2[t][1] + by);
            *(float2*)(dst + (size_t)rowA * EMBED_DIM + col) = o;
        }
        if (rowB < N_NODES) {
            float2 o;
            o.x = fast_tanh(d[t][2] + d2[t][2] + bx);
            o.y = fast_tanh(d[t][3] + d2[t][3] + by);
            *(float2*)(dst + (size_t)rowB * EMBED_DIM + col) = o;
        }
    }
}

extern "C" void kernel_launch(void* const* d_in, const int* in_sizes, int n_in,
                              void* d_out, int out_size) {
    const float* x  = (const float*)d_in[0];
    const int*   ei = (const int*)d_in[1];
    const float* W1 = (const float*)d_in[2];
    const float* b1 = (const float*)d_in[3];
    const float* W2 = (const float*)d_in[4];
    const float* b2 = (const float*)d_in[5];
    float* out = (float*)d_out;

    cudaFuncSetAttribute(k_mma_gemm,
                         cudaFuncAttributeMaxDynamicSharedMemorySize, MMA_SMEM);

    const int NT = 256;
    int blksE  = (N_EDGES + NT - 1) / NT;        // 1954
    int blksND = (N_NODES * 32 + NT - 1) / NT;   // 6250

    // CSR build (g_cnt zero at entry; self-cleaned in scan)
    k_hist<<<blksE, NT>>>(ei, W1, W2);
    k_blocksum<<<NBLK, NT>>>();
    k_scan_final<<<NBLK, NT>>>();
    k_fill<<<blksE, NT>>>(ei);

    float* out2 = (out_size >= 2 * N_NODES * EMBED_DIM)
                ? out + (size_t)N_NODES * EMBED_DIM : nullptr;

    // layer 1 (gather also writes the identity copy of x)
    k_gather<<<blksND, NT>>>(x, 0, out2);
    k_mma_gemm<<<N_TILES, NT, MMA_SMEM>>>(b1, out, 0, 1);

    // layer 2
    k_gather<<<blksND, NT>>>(x, 1, nullptr);
    k_mma_gemm<<<N_TILES, NT, MMA_SMEM>>>(b2, out, 1, 0);
}

// round 17
// speedup vs baseline: 1.0874x; 1.0125x over previous
#include <cuda_runtime.h>
#include <cuda_bf16.h>
#include <cstdint>

#define N_NODES 50000
#define EMBED_DIM 128
#define N_EDGES 500000
#define NBLK ((N_NODES + 255) / 256)   // 196
#define N_TILES ((N_NODES + 63) / 64)  // 782
#define N_ROWS_PAD (N_TILES * 64)      // 50048

// ---------------- device scratch (zero-initialized at module load) ----------------
__device__ int   g_cnt[N_NODES];          // self-cleaning histogram
__device__ int   g_bsum[NBLK];
__device__ int   g_rowstart[N_NODES + 1];
__device__ int   g_cursor[N_NODES];
__device__ unsigned long long g_edge[N_EDGES];   // packed {val_f32<<32 | col}
__device__ float g_dis[N_NODES];
__device__ __nv_bfloat16 g_aggh[N_ROWS_PAD * EMBED_DIM];  // agg hi image
__device__ __nv_bfloat16 g_aggl[N_ROWS_PAD * EMBED_DIM];  // agg lo image
__device__ float g_h[N_NODES * EMBED_DIM];
// W split images, transposed: Bh[layer][n*128+k] = bf16_hi(W[k][n])
__device__ __nv_bfloat16 g_Bh[2][128 * 128];
__device__ __nv_bfloat16 g_Bl[2][128 * 128];

__device__ __forceinline__ float fast_tanh(float x) {
    float y;
    asm("tanh.approx.f32 %0, %1;" : "=f"(y) : "f"(x));
    return y;
}

// ---------------- hist (1 edge/thread, fused weight prep) ----------------
__global__ void k_hist(const int* __restrict__ ei,
                       const float* __restrict__ W1, const float* __restrict__ W2) {
    int e = blockIdx.x * blockDim.x + threadIdx.x;
    if (e < N_EDGES) {
        unsigned d = (unsigned)ei[N_EDGES + e];
        if (d < N_NODES) atomicAdd(&g_cnt[d], 1);
    }
    if (blockIdx.x < 128) {
        int idx = blockIdx.x * blockDim.x + threadIdx.x;
        int layer = idx >> 14;
        int t = idx & 16383;
        int k = t >> 7, n = t & 127;
        const float* W = layer ? W2 : W1;
        float w = W[k * 128 + n];
        __nv_bfloat16 wh = __float2bfloat16(w);
        __nv_bfloat16 wl = __float2bfloat16(w - __bfloat162float(wh));
        g_Bh[layer][n * 128 + k] = wh;
        g_Bl[layer][n * 128 + k] = wl;
    }
}

// ---------------- warp-shuffle block sum ----------------
__global__ __launch_bounds__(256) void k_blocksum() {
    int t = threadIdx.x;
    int i = blockIdx.x * 256 + t;
    int v = (i < N_NODES) ? g_cnt[i] : 0;
    #pragma unroll
    for (int off = 16; off > 0; off >>= 1) v += __shfl_down_sync(0xffffffffu, v, off);
    __shared__ int ws[8];
    if ((t & 31) == 0) ws[t >> 5] = v;
    __syncthreads();
    if (t == 0) {
        int s = 0;
        #pragma unroll
        for (int w = 0; w < 8; w++) s += ws[w];
        g_bsum[blockIdx.x] = s;
    }
}

// ---------------- warp-shuffle scan (2 barriers) ----------------
__global__ __launch_bounds__(256) void k_scan_final() {
    int t = threadIdx.x;
    int lane = t & 31, warp = t >> 5;
    int i = blockIdx.x * 256 + t;

    int b = (t < blockIdx.x) ? g_bsum[t] : 0;
    #pragma unroll
    for (int off = 16; off > 0; off >>= 1) b += __shfl_down_sync(0xffffffffu, b, off);
    __shared__ int ws[8], wt[8], s_blockoff;
    if (lane == 0) ws[warp] = b;

    int v = (i < N_NODES) ? g_cnt[i] : 0;
    int incl = v;
    #pragma unroll
    for (int off = 1; off < 32; off <<= 1) {
        int n = __shfl_up_sync(0xffffffffu, incl, off);
        if (lane >= off) incl += n;
    }
    if (lane == 31) wt[warp] = incl;
    __syncthreads();
    if (t == 0) {
        int s = 0;
        #pragma unroll
        for (int w = 0; w < 8; w++) s += ws[w];
        s_blockoff = s;
    }
    __syncthreads();
    int warpbase = 0;
    #pragma unroll
    for (int w = 0; w < 8; w++) if (w < warp) warpbase += wt[w];

    if (i < N_NODES) {
        int rs = s_blockoff + warpbase + incl - v;
        g_rowstart[i] = rs;
        g_cursor[i]   = rs;
        g_dis[i]      = rsqrtf((float)(v + 1));
        g_cnt[i]      = 0;
    }
    if (i == 0) g_rowstart[N_NODES] = N_EDGES;
}

// ---------------- fill (1 edge/thread) ----------------
__global__ void k_fill(const int* __restrict__ ei) {
    int e = blockIdx.x * blockDim.x + threadIdx.x;
    if (e >= N_EDGES) return;
    unsigned s = (unsigned)ei[e];
    unsigned d = (unsigned)ei[N_EDGES + e];
    if (s >= N_NODES || d >= N_NODES) return;
    int pos = atomicAdd(&g_cursor[d], 1);
    float nm = g_dis[s] * g_dis[d];
    g_edge[pos] = ((unsigned long long)__float_as_uint(nm) << 32) | (unsigned long long)s;
}

// ---------------- gather-aggregate (warp per node); writes split bf16 images ----------------
__global__ __launch_bounds__(256) void k_gather(const float* __restrict__ x, int use_h,
                                                float* __restrict__ out2) {
    int idx = blockIdx.x * blockDim.x + threadIdx.x;
    int node = idx >> 5;
    if (node >= N_NODES) return;
    const float* in = use_h ? g_h : x;
    int lane = idx & 31;

    float di = g_dis[node];
    float c = di * di;
    float4 raw = ((const float4*)(in + (size_t)node * EMBED_DIM))[lane];
    if (out2) ((float4*)(out2 + (size_t)node * EMBED_DIM))[lane] = raw;
    float4 acc;
    acc.x = raw.x * c; acc.y = raw.y * c; acc.z = raw.z * c; acc.w = raw.w * c;

    int j   = g_rowstart[node];
    int end = g_rowstart[node + 1];

    for (; j + 4 <= end; j += 4) {
        unsigned long long p0 = g_edge[j],     p1 = g_edge[j + 1];
        unsigned long long p2 = g_edge[j + 2], p3 = g_edge[j + 3];
        int s0 = (int)(unsigned)p0, s1 = (int)(unsigned)p1;
        int s2 = (int)(unsigned)p2, s3 = (int)(unsigned)p3;
        float n0 = __uint_as_float((unsigned)(p0 >> 32));
        float n1 = __uint_as_float((unsigned)(p1 >> 32));
        float n2 = __uint_as_float((unsigned)(p2 >> 32));
        float n3 = __uint_as_float((unsigned)(p3 >> 32));
        float4 v0 = ((const float4*)(in + (size_t)s0 * EMBED_DIM))[lane];
        float4 v1 = ((const float4*)(in + (size_t)s1 * EMBED_DIM))[lane];
        float4 v2 = ((const float4*)(in + (size_t)s2 * EMBED_DIM))[lane];
        float4 v3 = ((const float4*)(in + (size_t)s3 * EMBED_DIM))[lane];
        acc.x += n0 * v0.x + n1 * v1.x + n2 * v2.x + n3 * v3.x;
        acc.y += n0 * v0.y + n1 * v1.y + n2 * v2.y + n3 * v3.y;
        acc.z += n0 * v0.z + n1 * v1.z + n2 * v2.z + n3 * v3.z;
        acc.w += n0 * v0.w + n1 * v1.w + n2 * v2.w + n3 * v3.w;
    }
    for (; j < end; j++) {
        unsigned long long p0 = g_edge[j];
        int s0 = (int)(unsigned)p0;
        float n0 = __uint_as_float((unsigned)(p0 >> 32));
        float4 v0 = ((const float4*)(in + (size_t)s0 * EMBED_DIM))[lane];
        acc.x += n0 * v0.x; acc.y += n0 * v0.y;
        acc.z += n0 * v0.z; acc.w += n0 * v0.w;
    }

    union { __nv_bfloat16 h[4]; uint2 u; } ph, pl;
    float av[4] = {acc.x, acc.y, acc.z, acc.w};
    #pragma unroll
    for (int q = 0; q < 4; q++) {
        __nv_bfloat16 hh = __float2bfloat16(av[q]);
        ph.h[q] = hh;
        pl.h[q] = __float2bfloat16(av[q] - __bfloat162float(hh));
    }
    ((uint2*)(g_aggh + (size_t)node * EMBED_DIM))[lane] = ph.u;
    ((uint2*)(g_aggl + (size_t)node * EMBED_DIM))[lane] = pl.u;
}

// ---------------- HMMA bf16x3 GEMM + bias + fast tanh (64x64 tiles, 3 CTAs/SM) ----------------
#define PAD 136
#define A_IMG (64 * PAD * 2)     // 17408
#define BH_IMG (64 * PAD * 2)    // 17408 (64 n-rows per CTA)
#define SM_AH 0
#define SM_AL A_IMG
#define SM_BH (2 * A_IMG)
#define SM_BL (2 * A_IMG + BH_IMG)
#define MMA_SMEM (2 * A_IMG + 2 * BH_IMG)   // 69632 B -> 3 CTAs/SM

__device__ __forceinline__ uint32_t smem_u32(const void* p) {
    uint32_t a;
    asm("{ .reg .u64 t; cvta.to.shared.u64 t, %1; cvt.u32.u64 %0, t; }" : "=r"(a) : "l"(p));
    return a;
}
__device__ __forceinline__ void ldm_x4(uint32_t* r, uint32_t addr) {
    asm volatile("ldmatrix.sync.aligned.m8n8.x4.shared.b16 {%0,%1,%2,%3}, [%4];"
                 : "=r"(r[0]), "=r"(r[1]), "=r"(r[2]), "=r"(r[3]) : "r"(addr));
}
__device__ __forceinline__ void mma_bf16(float* d, const uint32_t* a, uint32_t b0, uint32_t b1) {
    asm volatile(
        "mma.sync.aligned.m16n8k16.row.col.f32.bf16.bf16.f32 "
        "{%0,%1,%2,%3}, {%4,%5,%6,%7}, {%8,%9}, {%0,%1,%2,%3};"
        : "+f"(d[0]), "+f"(d[1]), "+f"(d[2]), "+f"(d[3])
        : "r"(a[0]), "r"(a[1]), "r"(a[2]), "r"(a[3]), "r"(b0), "r"(b1));
}

__global__ __launch_bounds__(256, 3) void k_mma_gemm(const float* __restrict__ bvec,
                                                     float* __restrict__ out,
                                                     int layer, int to_h) {
    extern __shared__ char sm[];
    int tid = threadIdx.x, wid = tid >> 5, lane = tid & 31;
    int row0   = (blockIdx.x >> 1) * 64;
    int cta_n0 = (blockIdx.x & 1) * 64;      // CTA covers cols cta_n0..+63
    float* dst = to_h ? g_h : out;

    // stage B half-images (64 n-rows): 1024 uint4 per image
    {
        const uint4* bh = (const uint4*)(g_Bh[layer] + (size_t)cta_n0 * 128);
        const uint4* bl = (const uint4*)(g_Bl[layer] + (size_t)cta_n0 * 128);
        #pragma unroll
        for (int i = 0; i < 4; i++) {
            int idx = tid + i * 256;
            int n = idx >> 4, c = idx & 15;
            *(uint4*)(sm + SM_BH + n * (PAD * 2) + c * 16) = bh[idx];
            *(uint4*)(sm + SM_BL + n * (PAD * 2) + c * 16) = bl[idx];
        }
    }
    // stage A images (pure copies; padding rows zero)
    {
        const uint4* ah = (const uint4*)(g_aggh + (size_t)row0 * EMBED_DIM);
        const uint4* al = (const uint4*)(g_aggl + (size_t)row0 * EMBED_DIM);
        #pragma unroll
        for (int i = 0; i < 4; i++) {
            int idx = tid + i * 256;
            int r = idx >> 4, c = idx & 15;
            *(uint4*)(sm + SM_AH + r * (PAD * 2) + c * 16) = ah[idx];
            *(uint4*)(sm + SM_AL + r * (PAD * 2) + c * 16) = al[idx];
        }
    }
    __syncthreads();

    int m0 = (wid & 3) * 16;
    int n_sub = (wid >> 2) * 32;             // local n-offset within CTA half

    uint32_t sb = smem_u32(sm);
    uint32_t aoff = (uint32_t)((m0 + (lane & 15)) * (PAD * 2) + (lane & 16));
    uint32_t aAddrH = sb + SM_AH + aoff;
    uint32_t aAddrL = sb + SM_AL + aoff;
    uint32_t bAddrH[2], bAddrL[2];
    #pragma unroll
    for (int p = 0; p < 2; p++) {
        int n = n_sub + p * 16 + (lane & 7) + ((lane >> 1) & 8);
        uint32_t boff = (uint32_t)(n * (PAD * 2) + (lane & 8) * 2);
        bAddrH[p] = sb + SM_BH + boff;
        bAddrL[p] = sb + SM_BL + boff;
    }

    float d[4][4], d2[4][4];
    #pragma unroll
    for (int t = 0; t < 4; t++)
        #pragma unroll
        for (int q = 0; q < 4; q++) { d[t][q] = 0.0f; d2[t][q] = 0.0f; }

    #pragma unroll
    for (int kk = 0; kk < 8; kk++) {
        uint32_t kb = kk * 32;
        uint32_t ah[4], al[4], bh[2][4], bl[2][4];
        ldm_x4(ah, aAddrH + kb);
        ldm_x4(al, aAddrL + kb);
        #pragma unroll
        for (int p = 0; p < 2; p++) {
            ldm_x4(bh[p], bAddrH[p] + kb);
            ldm_x4(bl[p], bAddrL[p] + kb);
        }
        #pragma unroll
        for (int p = 0; p < 2; p++) {
            #pragma unroll
            for (int q = 0; q < 2; q++) {
                int t = p * 2 + q;
                mma_bf16(d[t],  ah, bh[p][2 * q], bh[p][2 * q + 1]);   // Ah*Bh
                mma_bf16(d2[t], ah, bl[p][2 * q], bl[p][2 * q + 1]);   // Ah*Bl
                mma_bf16(d2[t], al, bh[p][2 * q], bh[p][2 * q + 1]);   // Al*Bh
            }
        }
    }

    int g = lane >> 2;
    int c2 = (lane & 3) * 2;
    int rowA = row0 + m0 + g;
    int rowB = rowA + 8;
    #pragma unroll
    for (int t = 0; t < 4; t++) {
        int col = cta_n0 + n_sub + t * 8 + c2;
        float bx = bvec[col], by = bvec[col + 1];
        if (rowA < N_NODES) {
            float2 o;
            o.x = fast_tanh(d[t][0] + d2[t][0] + bx);
            o.y = fast_tanh(d[t][1] + d2[t][1] + by);
            *(float2*)(dst + (size_t)rowA * EMBED_DIM + col) = o;
        }
        if (rowB < N_NODES) {
            float2 o;
            o.x = fast_tanh(d[t][2] + d2[t][2] + bx);
            o.y = fast_tanh(d[t][3] + d2[t][3] + by);
            *(float2*)(dst + (size_t)rowB * EMBED_DIM + col) = o;
        }
    }
}

extern "C" void kernel_launch(void* const* d_in, const int* in_sizes, int n_in,
                              void* d_out, int out_size) {
    const float* x  = (const float*)d_in[0];
    const int*   ei = (const int*)d_in[1];
    const float* W1 = (const float*)d_in[2];
    const float* b1 = (const float*)d_in[3];
    const float* W2 = (const float*)d_in[4];
    const float* b2 = (const float*)d_in[5];
    float* out = (float*)d_out;

    cudaFuncSetAttribute(k_mma_gemm,
                         cudaFuncAttributeMaxDynamicSharedMemorySize, MMA_SMEM);

    const int NT = 256;
    int blksE  = (N_EDGES + NT - 1) / NT;        // 1954
    int blksND = (N_NODES * 32 + NT - 1) / NT;   // 6250
    int blksG  = N_TILES * 2;                    // 1564 (64x64 tiles)

    // CSR build (g_cnt zero at entry; self-cleaned in scan)
    k_hist<<<blksE, NT>>>(ei, W1, W2);
    k_blocksum<<<NBLK, NT>>>();
    k_scan_final<<<NBLK, NT>>>();
    k_fill<<<blksE, NT>>>(ei);

    float* out2 = (out_size >= 2 * N_NODES * EMBED_DIM)
                ? out + (size_t)N_NODES * EMBED_DIM : nullptr;

    // layer 1 (gather also writes the identity copy of x)
    k_gather<<<blksND, NT>>>(x, 0, out2);
    k_mma_gemm<<<blksG, NT, MMA_SMEM>>>(b1, out, 0, 1);

    // layer 2
    k_gather<<<blksND, NT>>>(x, 1, nullptr);
    k_mma_gemm<<<blksG, NT, MMA_SMEM>>>(b2, out, 1, 0);
}